// round 6
// baseline (speedup 1.0000x reference)
#include <cuda_runtime.h>

typedef unsigned long long u64;

#define HW 4096          // h*w tokens
#define NH 8             // heads
#define TM 512           // key tile per smem stage

// ---- scratch (device globals; no allocation allowed) ----
__device__ float4 g_q[NH * HW * 2];   // [h][n][8] as 2x float4, L2-normalized
__device__ float4 g_k[NH * HW * 2];   // [h][m][8], L2-normalized
__device__ float4 g_v[NH * HW * 2];   // [h][m][8]
__device__ float  g_o[64 * HW];       // attention output, [c][p] layout

// ---- packed f32x2 helpers (ptxas won't auto-fuse; PTX-only path) ----
__device__ __forceinline__ u64 pack2(float a, float b) {
    u64 r; asm("mov.b64 %0,{%1,%2};" : "=l"(r) : "f"(a), "f"(b)); return r;
}
__device__ __forceinline__ void unpack2(u64 v, float& a, float& b) {
    asm("mov.b64 {%0,%1},%2;" : "=f"(a), "=f"(b) : "l"(v));
}
__device__ __forceinline__ u64 ffma2(u64 a, u64 b, u64 c) {
    u64 d; asm("fma.rn.f32x2 %0,%1,%2,%3;" : "=l"(d) : "l"(a), "l"(b), "l"(c)); return d;
}
__device__ __forceinline__ u64 fmul2(u64 a, u64 b) {
    u64 d; asm("mul.rn.f32x2 %0,%1,%2;" : "=l"(d) : "l"(a), "l"(b)); return d;
}
__device__ __forceinline__ float ex2f(float x) {
    float r; asm("ex2.approx.ftz.f32 %0,%1;" : "=f"(r) : "f"(x)); return r;
}

// ============================================================================
// Kernel 1: q/k/v projection + per-head L2 normalization of q,k.
// One thread per pixel. Weights staged in smem (reused buffer: wq then wkv).
// ============================================================================
__global__ __launch_bounds__(64)
void prep_kernel(const float* __restrict__ x, const float* __restrict__ y,
                 const float* __restrict__ wq, const float* __restrict__ wkv) {
    __shared__ float4 sW[2048];   // 32 KB, holds wq (1024 f4) then wkv (2048 f4)
    const int tid = threadIdx.x;
    const int p   = blockIdx.x * 64 + tid;

    // ---- phase 1: q = wq @ x, normalize per head ----
    for (int i = tid; i < 1024; i += 64) sW[i] = ((const float4*)wq)[i];
    __syncthreads();

    float xr[64];
#pragma unroll
    for (int c = 0; c < 64; c++) xr[c] = x[c * HW + p];   // coalesced

#pragma unroll
    for (int h = 0; h < 8; h++) {
        float qd[8]; float ss = 0.f;
#pragma unroll
        for (int d = 0; d < 8; d++) {
            const int o = h * 8 + d; float acc = 0.f;
#pragma unroll
            for (int c4 = 0; c4 < 16; c4++) {
                float4 w = sW[o * 16 + c4];
                acc += w.x * xr[c4 * 4 + 0] + w.y * xr[c4 * 4 + 1]
                     + w.z * xr[c4 * 4 + 2] + w.w * xr[c4 * 4 + 3];
            }
            qd[d] = acc; ss += acc * acc;
        }
        const float inv = 1.f / fmaxf(sqrtf(ss), 1e-12f);
        g_q[(h * HW + p) * 2 + 0] = make_float4(qd[0]*inv, qd[1]*inv, qd[2]*inv, qd[3]*inv);
        g_q[(h * HW + p) * 2 + 1] = make_float4(qd[4]*inv, qd[5]*inv, qd[6]*inv, qd[7]*inv);
    }
    __syncthreads();   // protect sW before overwrite

    // ---- phase 2: kv = wkv @ y; k = rows 0..63 (normalize), v = rows 64..127 ----
    for (int i = tid; i < 2048; i += 64) sW[i] = ((const float4*)wkv)[i];
    __syncthreads();

#pragma unroll
    for (int c = 0; c < 64; c++) xr[c] = y[c * HW + p];

#pragma unroll
    for (int h = 0; h < 8; h++) {
        float kd[8]; float ss = 0.f;
#pragma unroll
        for (int d = 0; d < 8; d++) {
            const int o = h * 8 + d; float acc = 0.f;
#pragma unroll
            for (int c4 = 0; c4 < 16; c4++) {
                float4 w = sW[o * 16 + c4];
                acc += w.x * xr[c4 * 4 + 0] + w.y * xr[c4 * 4 + 1]
                     + w.z * xr[c4 * 4 + 2] + w.w * xr[c4 * 4 + 3];
            }
            kd[d] = acc; ss += acc * acc;
        }
        const float inv = 1.f / fmaxf(sqrtf(ss), 1e-12f);
        g_k[(h * HW + p) * 2 + 0] = make_float4(kd[0]*inv, kd[1]*inv, kd[2]*inv, kd[3]*inv);
        g_k[(h * HW + p) * 2 + 1] = make_float4(kd[4]*inv, kd[5]*inv, kd[6]*inv, kd[7]*inv);

        float vd[8];
#pragma unroll
        for (int d = 0; d < 8; d++) {
            const int o = 64 + h * 8 + d; float acc = 0.f;
#pragma unroll
            for (int c4 = 0; c4 < 16; c4++) {
                float4 w = sW[o * 16 + c4];
                acc += w.x * xr[c4 * 4 + 0] + w.y * xr[c4 * 4 + 1]
                     + w.z * xr[c4 * 4 + 2] + w.w * xr[c4 * 4 + 3];
            }
            vd[d] = acc;
        }
        g_v[(h * HW + p) * 2 + 0] = make_float4(vd[0], vd[1], vd[2], vd[3]);
        g_v[(h * HW + p) * 2 + 1] = make_float4(vd[4], vd[5], vd[6], vd[7]);
    }
}

// ============================================================================
// Kernel 2: streaming attention. One thread = one (head, query).
// Logits bounded by |T_h| (cosine sim), so one-pass softmax with constant
// bias -|T_h| is exact: e = exp(T*dot - |T|); out = (sum e*v) / (sum e).
// Core math in packed f32x2 FMAs, exp via MUFU ex2.approx.
// grid = 8 heads x 16 query-blocks = 128 blocks x 256 threads.
// ============================================================================
__global__ __launch_bounds__(256)
void attn_kernel(const float* __restrict__ temperature) {
    __shared__ ulonglong2 sK[TM * 2];   // per key m: {k01,k23},{k45,k67} -> 16 KB
    __shared__ ulonglong2 sV[TM * 2];   // 16 KB

    const int h   = blockIdx.x >> 4;
    const int qb  = blockIdx.x & 15;
    const int tid = threadIdx.x;
    const int n   = qb * 256 + tid;

    // query registers, packed
    const float4 qf0 = g_q[((size_t)h * HW + n) * 2 + 0];
    const float4 qf1 = g_q[((size_t)h * HW + n) * 2 + 1];
    const u64 q01 = pack2(qf0.x, qf0.y), q23 = pack2(qf0.z, qf0.w);
    const u64 q45 = pack2(qf1.x, qf1.y), q67 = pack2(qf1.z, qf1.w);

    u64 a01 = pack2(0.f, 0.f), a23 = a01, a45 = a01, a67 = a01;
    float den = 0.f;

    const float T    = temperature[h];
    const float tl2  = T * 1.4426950408889634f;            // T * log2(e)
    const float bias = -fabsf(T) * 1.4426950408889634f;    // -|T| * log2(e)

    const ulonglong2* __restrict__ gK = (const ulonglong2*)g_k + (size_t)h * HW * 2;
    const ulonglong2* __restrict__ gV = (const ulonglong2*)g_v + (size_t)h * HW * 2;

    for (int t = 0; t < HW; t += TM) {
        __syncthreads();
#pragma unroll
        for (int i = tid; i < TM * 2; i += 256) {
            sK[i] = gK[(size_t)t * 2 + i];
            sV[i] = gV[(size_t)t * 2 + i];
        }
        __syncthreads();

#pragma unroll 4
        for (int j = 0; j < TM; j++) {
            const ulonglong2 k0 = sK[2 * j], k1 = sK[2 * j + 1];   // broadcast LDS
            const ulonglong2 v0 = sV[2 * j], v1 = sV[2 * j + 1];

            u64 d = fmul2(q01, k0.x);
            d = ffma2(q23, k0.y, d);
            d = ffma2(q45, k1.x, d);
            d = ffma2(q67, k1.y, d);
            float lo, hi; unpack2(d, lo, hi);

            const float e = ex2f(fmaf(lo + hi, tl2, bias));
            den += e;
            const u64 ee = pack2(e, e);
            a01 = ffma2(ee, v0.x, a01);
            a23 = ffma2(ee, v0.y, a23);
            a45 = ffma2(ee, v1.x, a45);
            a67 = ffma2(ee, v1.y, a67);
        }
    }

    const float r = 1.0f / den;
    float o0, o1, o2, o3, o4, o5, o6, o7;
    unpack2(a01, o0, o1); unpack2(a23, o2, o3);
    unpack2(a45, o4, o5); unpack2(a67, o6, o7);

    float* go = g_o + (size_t)h * 8 * HW + n;   // [c][p], coalesced across n
    go[0 * HW] = o0 * r; go[1 * HW] = o1 * r;
    go[2 * HW] = o2 * r; go[3 * HW] = o3 * r;
    go[4 * HW] = o4 * r; go[5 * HW] = o5 * r;
    go[6 * HW] = o6 * r; go[7 * HW] = o7 * r;
}

// ============================================================================
// Kernel 3: output projection  out[o][p] = sum_c wout[o][c] * g_o[c][p]
// ============================================================================
__global__ __launch_bounds__(64)
void outproj_kernel(const float* __restrict__ wout, float* __restrict__ out) {
    __shared__ float4 sW[1024];   // 16 KB
    const int tid = threadIdx.x;
    const int p   = blockIdx.x * 64 + tid;

    for (int i = tid; i < 1024; i += 64) sW[i] = ((const float4*)wout)[i];
    __syncthreads();

    float xr[64];
#pragma unroll
    for (int c = 0; c < 64; c++) xr[c] = g_o[c * HW + p];

#pragma unroll
    for (int o = 0; o < 64; o++) {
        float acc = 0.f;
#pragma unroll
        for (int c4 = 0; c4 < 16; c4++) {
            float4 w = sW[o * 16 + c4];
            acc += w.x * xr[c4 * 4 + 0] + w.y * xr[c4 * 4 + 1]
                 + w.z * xr[c4 * 4 + 2] + w.w * xr[c4 * 4 + 3];
        }
        out[o * HW + p] = acc;
    }
}

// ============================================================================
extern "C" void kernel_launch(void* const* d_in, const int* in_sizes, int n_in,
                              void* d_out, int out_size) {
    const float* x    = (const float*)d_in[0];
    const float* y    = (const float*)d_in[1];
    const float* wq   = (const float*)d_in[2];
    const float* wkv  = (const float*)d_in[3];
    const float* wout = (const float*)d_in[4];
    const float* temp = (const float*)d_in[5];
    float* out = (float*)d_out;

    prep_kernel<<<64, 64>>>(x, y, wq, wkv);
    attn_kernel<<<128, 256>>>(temp);
    outproj_kernel<<<64, 64>>>(wout, out);
}

// round 7
// speedup vs baseline: 1.3719x; 1.3719x over previous
#include <cuda_runtime.h>

typedef unsigned long long u64;

#define HW 4096          // h*w tokens
#define NH 8             // heads
#define TM 512           // key tile per smem stage

// ---- scratch (device globals; no allocation allowed) ----
__device__ float4 g_q[NH * HW * 2];   // [h][n][8] as 2x float4, L2-normalized (pre-scaled later)
__device__ float4 g_k[NH * HW * 2];   // [h][m][8], L2-normalized
__device__ float4 g_v[NH * HW * 2];   // [h][m][8]
__device__ float  g_o[64 * HW];       // attention output, [c][p] layout

// ---- packed f32x2 helpers (ptxas won't auto-fuse; PTX-only path) ----
__device__ __forceinline__ u64 pack2(float a, float b) {
    u64 r; asm("mov.b64 %0,{%1,%2};" : "=l"(r) : "f"(a), "f"(b)); return r;
}
__device__ __forceinline__ void unpack2(u64 v, float& a, float& b) {
    asm("mov.b64 {%0,%1},%2;" : "=f"(a), "=f"(b) : "l"(v));
}
__device__ __forceinline__ u64 ffma2(u64 a, u64 b, u64 c) {
    u64 d; asm("fma.rn.f32x2 %0,%1,%2,%3;" : "=l"(d) : "l"(a), "l"(b), "l"(c)); return d;
}
__device__ __forceinline__ u64 fmul2(u64 a, u64 b) {
    u64 d; asm("mul.rn.f32x2 %0,%1,%2;" : "=l"(d) : "l"(a), "l"(b)); return d;
}
__device__ __forceinline__ float ex2f(float x) {
    float r; asm("ex2.approx.ftz.f32 %0,%1;" : "=f"(r) : "f"(x)); return r;
}

// ============================================================================
// Kernel 1: q/k/v projection + per-head L2 normalization of q,k.
// One thread per (pixel, head, type). grid = (4096/128, 24), block = 128.
// task = blockIdx.y:  0..7 -> q head t (from x, wq rows h*8..h*8+7)
//                     8..15 -> k head t-8 (from y, wkv rows h*8..)
//                    16..23 -> v head t-16 (from y, wkv rows 64+h*8..)
// Each block stages its 8 weight rows (128 float4 = 2 KB) in smem; warp-uniform
// reads broadcast. Input reads coalesced (p contiguous in warp).
// ============================================================================
__global__ __launch_bounds__(128)
void prep_kernel(const float* __restrict__ x, const float* __restrict__ y,
                 const float* __restrict__ wq, const float* __restrict__ wkv) {
    __shared__ float4 sW[128];
    const int tid  = threadIdx.x;
    const int p    = blockIdx.x * 128 + tid;
    const int task = blockIdx.y;
    const int typ  = task >> 3;      // 0=q, 1=k, 2=v
    const int h    = task & 7;

    const float4* wsrc;
    if (typ == 0)      wsrc = (const float4*)wq  + (h * 8) * 16;
    else if (typ == 1) wsrc = (const float4*)wkv + (h * 8) * 16;
    else               wsrc = (const float4*)wkv + (64 + h * 8) * 16;
    sW[tid] = wsrc[tid];
    __syncthreads();

    const float* __restrict__ src = (typ == 0) ? x : y;
    float xr[64];
#pragma unroll
    for (int c = 0; c < 64; c++) xr[c] = src[c * HW + p];   // coalesced

    float o[8]; float ss = 0.f;
#pragma unroll
    for (int d = 0; d < 8; d++) {
        float acc = 0.f;
#pragma unroll
        for (int c4 = 0; c4 < 16; c4++) {
            const float4 w = sW[d * 16 + c4];
            acc += w.x * xr[4 * c4 + 0] + w.y * xr[4 * c4 + 1]
                 + w.z * xr[4 * c4 + 2] + w.w * xr[4 * c4 + 3];
        }
        o[d] = acc; ss += acc * acc;
    }

    const float inv = (typ < 2) ? (1.f / fmaxf(sqrtf(ss), 1e-12f)) : 1.f;
    float4* dst = (typ == 0) ? g_q : ((typ == 1) ? g_k : g_v);
    dst[((size_t)h * HW + p) * 2 + 0] = make_float4(o[0]*inv, o[1]*inv, o[2]*inv, o[3]*inv);
    dst[((size_t)h * HW + p) * 2 + 1] = make_float4(o[4]*inv, o[5]*inv, o[6]*inv, o[7]*inv);
}

// ============================================================================
// Kernel 2: streaming attention. One thread = one (head, query).
// Logits are cosine similarities, bounded by |T_h|: one-pass softmax with a
// constant bias -|T_h| is exact (no row max, no rescale).
//   q' = q * (T*log2e)  (done once at load)
//   d  = q'.k + bias    (bias folded into the dot-chain initializer)
//   e  = ex2(d_lo + d_hi);  den += e;  acc += e * v
// Inner loop = 10 FMA-pipe instrs + 1 MUFU per key.
// grid = 8 heads x 16 query-blocks = 128 blocks x 256 threads.
// ============================================================================
__global__ __launch_bounds__(256)
void attn_kernel(const float* __restrict__ temperature) {
    __shared__ ulonglong2 sK[TM * 2];   // 16 KB
    __shared__ ulonglong2 sV[TM * 2];   // 16 KB

    const int h   = blockIdx.x >> 4;
    const int qb  = blockIdx.x & 15;
    const int tid = threadIdx.x;
    const int n   = qb * 256 + tid;

    const float T    = temperature[h];
    const float L2E  = 1.4426950408889634f;
    const float tl2  = T * L2E;
    const float bias = -fabsf(T) * L2E;

    // query registers, packed, pre-scaled by T*log2e
    const float4 qf0 = g_q[((size_t)h * HW + n) * 2 + 0];
    const float4 qf1 = g_q[((size_t)h * HW + n) * 2 + 1];
    const u64 tt  = pack2(tl2, tl2);
    const u64 q01 = fmul2(pack2(qf0.x, qf0.y), tt);
    const u64 q23 = fmul2(pack2(qf0.z, qf0.w), tt);
    const u64 q45 = fmul2(pack2(qf1.x, qf1.y), tt);
    const u64 q67 = fmul2(pack2(qf1.z, qf1.w), tt);
    const u64 dinit = pack2(bias, 0.f);

    u64 a01 = pack2(0.f, 0.f), a23 = a01, a45 = a01, a67 = a01;
    float den = 0.f;

    const ulonglong2* __restrict__ gK = (const ulonglong2*)g_k + (size_t)h * HW * 2;
    const ulonglong2* __restrict__ gV = (const ulonglong2*)g_v + (size_t)h * HW * 2;

    for (int t = 0; t < HW; t += TM) {
        __syncthreads();
#pragma unroll
        for (int i = tid; i < TM * 2; i += 256) {
            sK[i] = gK[(size_t)t * 2 + i];
            sV[i] = gV[(size_t)t * 2 + i];
        }
        __syncthreads();

#pragma unroll 4
        for (int j = 0; j < TM; j++) {
            const ulonglong2 k0 = sK[2 * j], k1 = sK[2 * j + 1];   // broadcast LDS
            const ulonglong2 v0 = sV[2 * j], v1 = sV[2 * j + 1];

            u64 d = ffma2(q01, k0.x, dinit);
            d = ffma2(q23, k0.y, d);
            d = ffma2(q45, k1.x, d);
            d = ffma2(q67, k1.y, d);
            float lo, hi; unpack2(d, lo, hi);

            const float e = ex2f(lo + hi);
            den += e;
            const u64 ee = pack2(e, e);
            a01 = ffma2(ee, v0.x, a01);
            a23 = ffma2(ee, v0.y, a23);
            a45 = ffma2(ee, v1.x, a45);
            a67 = ffma2(ee, v1.y, a67);
        }
    }

    const float r = 1.0f / den;
    float o0, o1, o2, o3, o4, o5, o6, o7;
    unpack2(a01, o0, o1); unpack2(a23, o2, o3);
    unpack2(a45, o4, o5); unpack2(a67, o6, o7);

    float* go = g_o + (size_t)h * 8 * HW + n;   // [c][p], coalesced across n
    go[0 * HW] = o0 * r; go[1 * HW] = o1 * r;
    go[2 * HW] = o2 * r; go[3 * HW] = o3 * r;
    go[4 * HW] = o4 * r; go[5 * HW] = o5 * r;
    go[6 * HW] = o6 * r; go[7 * HW] = o7 * r;
}

// ============================================================================
// Kernel 3: output projection. One thread per (pixel, 8-output group).
// grid = (4096/128, 8), block = 128.  out[o][p] = sum_c wout[o][c] * g_o[c][p]
// ============================================================================
__global__ __launch_bounds__(128)
void outproj_kernel(const float* __restrict__ wout, float* __restrict__ out) {
    __shared__ float4 sW[128];   // 8 rows x 16 float4 = 2 KB
    const int tid = threadIdx.x;
    const int p   = blockIdx.x * 128 + tid;
    const int og  = blockIdx.y;          // output rows og*8 .. og*8+7

    sW[tid] = ((const float4*)wout)[og * 128 + tid];
    __syncthreads();

    float xr[64];
#pragma unroll
    for (int c = 0; c < 64; c++) xr[c] = g_o[c * HW + p];

#pragma unroll
    for (int d = 0; d < 8; d++) {
        float acc = 0.f;
#pragma unroll
        for (int c4 = 0; c4 < 16; c4++) {
            const float4 w = sW[d * 16 + c4];
            acc += w.x * xr[4 * c4 + 0] + w.y * xr[4 * c4 + 1]
                 + w.z * xr[4 * c4 + 2] + w.w * xr[4 * c4 + 3];
        }
        out[(og * 8 + d) * HW + p] = acc;
    }
}

// ============================================================================
extern "C" void kernel_launch(void* const* d_in, const int* in_sizes, int n_in,
                              void* d_out, int out_size) {
    const float* x    = (const float*)d_in[0];
    const float* y    = (const float*)d_in[1];
    const float* wq   = (const float*)d_in[2];
    const float* wkv  = (const float*)d_in[3];
    const float* wout = (const float*)d_in[4];
    const float* temp = (const float*)d_in[5];
    float* out = (float*)d_out;

    prep_kernel<<<dim3(32, 24), 128>>>(x, y, wq, wkv);
    attn_kernel<<<128, 256>>>(temp);
    outproj_kernel<<<dim3(32, 8), 128>>>(wout, out);
}

// round 8
// speedup vs baseline: 1.6480x; 1.2013x over previous
#include <cuda_runtime.h>

typedef unsigned long long u64;

#define HW 4096          // h*w tokens
#define NH 8             // heads
#define TM 512           // key tile per smem stage
#define KSPLIT 4         // key-dimension split (partials add exactly: constant-bias softmax)

// ---- scratch (device globals; no allocation allowed) ----
__device__ float4 g_q[NH * HW * 2];            // [h][n][8], L2-normalized
__device__ float4 g_k[NH * HW * 2];            // [h][m][8], L2-normalized
__device__ float4 g_v[NH * HW * 2];            // [h][m][8]
__device__ float  g_pacc[KSPLIT * 64 * HW];    // partial acc: [s][h*8+d][n]
__device__ float  g_pden[KSPLIT * NH * HW];    // partial den: [s][h][n]
__device__ float  g_o[64 * HW];                // attention output, [c][p]

// ---- packed f32x2 helpers (ptxas won't auto-fuse; PTX-only path) ----
__device__ __forceinline__ u64 pack2(float a, float b) {
    u64 r; asm("mov.b64 %0,{%1,%2};" : "=l"(r) : "f"(a), "f"(b)); return r;
}
__device__ __forceinline__ void unpack2(u64 v, float& a, float& b) {
    asm("mov.b64 {%0,%1},%2;" : "=f"(a), "=f"(b) : "l"(v));
}
__device__ __forceinline__ u64 ffma2(u64 a, u64 b, u64 c) {
    u64 d; asm("fma.rn.f32x2 %0,%1,%2,%3;" : "=l"(d) : "l"(a), "l"(b), "l"(c)); return d;
}
__device__ __forceinline__ u64 fmul2(u64 a, u64 b) {
    u64 d; asm("mul.rn.f32x2 %0,%1,%2;" : "=l"(d) : "l"(a), "l"(b)); return d;
}
__device__ __forceinline__ float ex2f(float x) {
    float r; asm("ex2.approx.ftz.f32 %0,%1;" : "=f"(r) : "f"(x)); return r;
}

// ============================================================================
// Kernel 1: q/k/v projection + per-head L2 normalization of q,k.
// One thread per (pixel, head, type). grid = (32, 24), block = 128.
// ============================================================================
__global__ __launch_bounds__(128)
void prep_kernel(const float* __restrict__ x, const float* __restrict__ y,
                 const float* __restrict__ wq, const float* __restrict__ wkv) {
    __shared__ float4 sW[128];
    const int tid  = threadIdx.x;
    const int p    = blockIdx.x * 128 + tid;
    const int task = blockIdx.y;
    const int typ  = task >> 3;      // 0=q, 1=k, 2=v
    const int h    = task & 7;

    const float4* wsrc;
    if (typ == 0)      wsrc = (const float4*)wq  + (h * 8) * 16;
    else if (typ == 1) wsrc = (const float4*)wkv + (h * 8) * 16;
    else               wsrc = (const float4*)wkv + (64 + h * 8) * 16;
    sW[tid] = wsrc[tid];
    __syncthreads();

    const float* __restrict__ src = (typ == 0) ? x : y;
    float xr[64];
#pragma unroll
    for (int c = 0; c < 64; c++) xr[c] = src[c * HW + p];   // coalesced

    float o[8]; float ss = 0.f;
#pragma unroll
    for (int d = 0; d < 8; d++) {
        float acc = 0.f;
#pragma unroll
        for (int c4 = 0; c4 < 16; c4++) {
            const float4 w = sW[d * 16 + c4];
            acc += w.x * xr[4 * c4 + 0] + w.y * xr[4 * c4 + 1]
                 + w.z * xr[4 * c4 + 2] + w.w * xr[4 * c4 + 3];
        }
        o[d] = acc; ss += acc * acc;
    }

    const float inv = (typ < 2) ? (1.f / fmaxf(sqrtf(ss), 1e-12f)) : 1.f;
    float4* dst = (typ == 0) ? g_q : ((typ == 1) ? g_k : g_v);
    dst[((size_t)h * HW + p) * 2 + 0] = make_float4(o[0]*inv, o[1]*inv, o[2]*inv, o[3]*inv);
    dst[((size_t)h * HW + p) * 2 + 1] = make_float4(o[4]*inv, o[5]*inv, o[6]*inv, o[7]*inv);
}

// ============================================================================
// Kernel 2: streaming attention, key-split. One thread = one (head, query,
// key-slice). Logits are cosine sims bounded by |T_h|, so one-pass softmax
// with constant bias -|T_h| is exact AND partials across key slices combine
// by plain addition (no rescale).
// grid = (16 qblocks, 8 heads, KSPLIT), block = 256.
// ============================================================================
__global__ __launch_bounds__(256)
void attn_kernel(const float* __restrict__ temperature) {
    __shared__ ulonglong2 sK[TM * 2];   // 16 KB
    __shared__ ulonglong2 sV[TM * 2];   // 16 KB

    const int qb  = blockIdx.x;
    const int h   = blockIdx.y;
    const int s   = blockIdx.z;
    const int tid = threadIdx.x;
    const int n   = qb * 256 + tid;

    const float T    = temperature[h];
    const float L2E  = 1.4426950408889634f;
    const float tl2  = T * L2E;
    const float bias = -fabsf(T) * L2E;

    // query registers, packed, pre-scaled by T*log2e; bias folded into dot init
    const float4 qf0 = g_q[((size_t)h * HW + n) * 2 + 0];
    const float4 qf1 = g_q[((size_t)h * HW + n) * 2 + 1];
    const u64 tt  = pack2(tl2, tl2);
    const u64 q01 = fmul2(pack2(qf0.x, qf0.y), tt);
    const u64 q23 = fmul2(pack2(qf0.z, qf0.w), tt);
    const u64 q45 = fmul2(pack2(qf1.x, qf1.y), tt);
    const u64 q67 = fmul2(pack2(qf1.z, qf1.w), tt);
    const u64 dinit = pack2(bias, 0.f);

    u64 a01 = pack2(0.f, 0.f), a23 = a01, a45 = a01, a67 = a01;
    float den = 0.f;

    const int t0 = s * (HW / KSPLIT);
    const ulonglong2* __restrict__ gK = (const ulonglong2*)g_k + (size_t)h * HW * 2;
    const ulonglong2* __restrict__ gV = (const ulonglong2*)g_v + (size_t)h * HW * 2;

    for (int t = t0; t < t0 + HW / KSPLIT; t += TM) {
        __syncthreads();
#pragma unroll
        for (int i = tid; i < TM * 2; i += 256) {
            sK[i] = gK[(size_t)t * 2 + i];
            sV[i] = gV[(size_t)t * 2 + i];
        }
        __syncthreads();

#pragma unroll 4
        for (int j = 0; j < TM; j++) {
            const ulonglong2 k0 = sK[2 * j], k1 = sK[2 * j + 1];   // broadcast LDS
            const ulonglong2 v0 = sV[2 * j], v1 = sV[2 * j + 1];

            u64 d = ffma2(q01, k0.x, dinit);
            d = ffma2(q23, k0.y, d);
            d = ffma2(q45, k1.x, d);
            d = ffma2(q67, k1.y, d);
            float lo, hi; unpack2(d, lo, hi);

            const float e = ex2f(lo + hi);
            den += e;
            const u64 ee = pack2(e, e);
            a01 = ffma2(ee, v0.x, a01);
            a23 = ffma2(ee, v0.y, a23);
            a45 = ffma2(ee, v1.x, a45);
            a67 = ffma2(ee, v1.y, a67);
        }
    }

    float o0, o1, o2, o3, o4, o5, o6, o7;
    unpack2(a01, o0, o1); unpack2(a23, o2, o3);
    unpack2(a45, o4, o5); unpack2(a67, o6, o7);

    // partial writes, coalesced across n
    float* pa = g_pacc + ((size_t)s * 64 + h * 8) * HW + n;
    pa[0 * HW] = o0; pa[1 * HW] = o1; pa[2 * HW] = o2; pa[3 * HW] = o3;
    pa[4 * HW] = o4; pa[5 * HW] = o5; pa[6 * HW] = o6; pa[7 * HW] = o7;
    g_pden[((size_t)s * NH + h) * HW + n] = den;
}

// ============================================================================
// Kernel 2b: combine key-split partials, divide by total denominator.
// grid = (32, 8), block = 128. One thread per (head, pixel).
// ============================================================================
__global__ __launch_bounds__(128)
void reduce_kernel() {
    const int tid = threadIdx.x;
    const int p   = blockIdx.x * 128 + tid;
    const int h   = blockIdx.y;

    float acc[8];
#pragma unroll
    for (int d = 0; d < 8; d++) acc[d] = 0.f;
    float den = 0.f;

#pragma unroll
    for (int s = 0; s < KSPLIT; s++) {
        const float* pa = g_pacc + ((size_t)s * 64 + h * 8) * HW + p;
#pragma unroll
        for (int d = 0; d < 8; d++) acc[d] += pa[d * HW];
        den += g_pden[((size_t)s * NH + h) * HW + p];
    }

    const float r = 1.0f / den;
    float* go = g_o + (size_t)h * 8 * HW + p;
#pragma unroll
    for (int d = 0; d < 8; d++) go[d * HW] = acc[d] * r;
}

// ============================================================================
// Kernel 3: output projection. grid = (32, 8), block = 128.
// ============================================================================
__global__ __launch_bounds__(128)
void outproj_kernel(const float* __restrict__ wout, float* __restrict__ out) {
    __shared__ float4 sW[128];   // 8 rows x 16 float4 = 2 KB
    const int tid = threadIdx.x;
    const int p   = blockIdx.x * 128 + tid;
    const int og  = blockIdx.y;          // output rows og*8 .. og*8+7

    sW[tid] = ((const float4*)wout)[og * 128 + tid];
    __syncthreads();

    float xr[64];
#pragma unroll
    for (int c = 0; c < 64; c++) xr[c] = g_o[c * HW + p];

#pragma unroll
    for (int d = 0; d < 8; d++) {
        float acc = 0.f;
#pragma unroll
        for (int c4 = 0; c4 < 16; c4++) {
            const float4 w = sW[d * 16 + c4];
            acc += w.x * xr[4 * c4 + 0] + w.y * xr[4 * c4 + 1]
                 + w.z * xr[4 * c4 + 2] + w.w * xr[4 * c4 + 3];
        }
        out[(og * 8 + d) * HW + p] = acc;
    }
}

// ============================================================================
extern "C" void kernel_launch(void* const* d_in, const int* in_sizes, int n_in,
                              void* d_out, int out_size) {
    const float* x    = (const float*)d_in[0];
    const float* y    = (const float*)d_in[1];
    const float* wq   = (const float*)d_in[2];
    const float* wkv  = (const float*)d_in[3];
    const float* wout = (const float*)d_in[4];
    const float* temp = (const float*)d_in[5];
    float* out = (float*)d_out;

    prep_kernel<<<dim3(32, 24), 128>>>(x, y, wq, wkv);
    attn_kernel<<<dim3(16, 8, KSPLIT), 256>>>(temp);
    reduce_kernel<<<dim3(32, 8), 128>>>();
    outproj_kernel<<<dim3(32, 8), 128>>>(wout, out);
}

// round 9
// speedup vs baseline: 5.2772x; 3.2021x over previous
#include <cuda_runtime.h>
#include <cuda_fp16.h>

#define HW 4096          // tokens
#define NH 8             // heads
#define CHUNK 256        // keys per smem stage
#define CPAD 132         // padded uint stride for V^T rows (CHUNK/2 + 4)

// ---- scratch (device globals; no allocation allowed) ----
__device__ __align__(16) __half g_qh[NH * HW * 8];  // [h][n][8] f16, L2-norm * T*log2e
__device__ __align__(16) __half g_kh[NH * HW * 8];  // [h][m][8] f16, L2-norm
__device__ __align__(16) __half g_vt[NH * 8 * HW];  // [h][d][m] f16 (V transposed)
__device__ float g_o[64 * HW];                      // attention output, [c][p]

__device__ __forceinline__ float ex2f(float x) {
    float r; asm("ex2.approx.ftz.f32 %0,%1;" : "=f"(r) : "f"(x)); return r;
}
// pack two f32 -> f16x2  (PTX: cvt d, hi, lo  => d.lo = cvt(lo), d.hi = cvt(hi))
__device__ __forceinline__ unsigned packh2(float lo, float hi) {
    unsigned r; asm("cvt.rn.f16x2.f32 %0,%1,%2;" : "=r"(r) : "f"(hi), "f"(lo)); return r;
}
// S-mma: m16n8k8 f16 inputs, f32 accumulate
__device__ __forceinline__ void mma_s(float& d0, float& d1, float& d2, float& d3,
                                      unsigned a0, unsigned a1, unsigned b0,
                                      float c) {
    asm("mma.sync.aligned.m16n8k8.row.col.f32.f16.f16.f32 "
        "{%0,%1,%2,%3},{%4,%5},{%6},{%7,%7,%7,%7};"
        : "=f"(d0), "=f"(d1), "=f"(d2), "=f"(d3)
        : "r"(a0), "r"(a1), "r"(b0), "f"(c));
}
// PV-mma: m16n8k16, accumulates in place
__device__ __forceinline__ void mma_pv(float& d0, float& d1, float& d2, float& d3,
                                       unsigned a0, unsigned a1, unsigned a2, unsigned a3,
                                       unsigned b0, unsigned b1) {
    asm("mma.sync.aligned.m16n8k16.row.col.f32.f16.f16.f32 "
        "{%0,%1,%2,%3},{%4,%5,%6,%7},{%8,%9},{%0,%1,%2,%3};"
        : "+f"(d0), "+f"(d1), "+f"(d2), "+f"(d3)
        : "r"(a0), "r"(a1), "r"(a2), "r"(a3), "r"(b0), "r"(b1));
}

// ============================================================================
// Kernel 1: q/k/v projection + per-head L2 norm; emit f16.
// q pre-scaled by T*log2e; v written TRANSPOSED [h][d][m].
// grid = (32, 24), block = 128.  task y: 0..7 q, 8..15 k, 16..23 v.
// ============================================================================
__global__ __launch_bounds__(128)
void prep_kernel(const float* __restrict__ x, const float* __restrict__ y,
                 const float* __restrict__ wq, const float* __restrict__ wkv,
                 const float* __restrict__ temperature) {
    __shared__ float4 sW[128];
    const int tid  = threadIdx.x;
    const int p    = blockIdx.x * 128 + tid;
    const int task = blockIdx.y;
    const int typ  = task >> 3;      // 0=q, 1=k, 2=v
    const int h    = task & 7;

    const float4* wsrc;
    if (typ == 0)      wsrc = (const float4*)wq  + (h * 8) * 16;
    else if (typ == 1) wsrc = (const float4*)wkv + (h * 8) * 16;
    else               wsrc = (const float4*)wkv + (64 + h * 8) * 16;
    sW[tid] = wsrc[tid];
    __syncthreads();

    const float* __restrict__ src = (typ == 0) ? x : y;
    float xr[64];
#pragma unroll
    for (int c = 0; c < 64; c++) xr[c] = src[c * HW + p];   // coalesced

    float o[8]; float ss = 0.f;
#pragma unroll
    for (int d = 0; d < 8; d++) {
        float acc = 0.f;
#pragma unroll
        for (int c4 = 0; c4 < 16; c4++) {
            const float4 w = sW[d * 16 + c4];
            acc += w.x * xr[4 * c4 + 0] + w.y * xr[4 * c4 + 1]
                 + w.z * xr[4 * c4 + 2] + w.w * xr[4 * c4 + 3];
        }
        o[d] = acc; ss += acc * acc;
    }

    if (typ == 2) {
        // V: transpose store, coalesced across lanes per dim row
#pragma unroll
        for (int d = 0; d < 8; d++)
            g_vt[((size_t)h * 8 + d) * HW + p] = __float2half_rn(o[d]);
        return;
    }

    float scale = 1.f / fmaxf(sqrtf(ss), 1e-12f);
    if (typ == 0) scale *= temperature[h] * 1.4426950408889634f;

    __half2 h01 = __floats2half2_rn(o[0] * scale, o[1] * scale);
    __half2 h23 = __floats2half2_rn(o[2] * scale, o[3] * scale);
    __half2 h45 = __floats2half2_rn(o[4] * scale, o[5] * scale);
    __half2 h67 = __floats2half2_rn(o[6] * scale, o[7] * scale);
    uint4 row;
    row.x = *(unsigned*)&h01; row.y = *(unsigned*)&h23;
    row.z = *(unsigned*)&h45; row.w = *(unsigned*)&h67;
    uint4* dst = (typ == 0) ? (uint4*)g_qh : (uint4*)g_kh;
    dst[(size_t)h * HW + p] = row;   // 16 B per token row
}

// ============================================================================
// Kernel 2: flash attention on HMMA. Block = 256 thr (8 warps), each warp
// owns 16 queries; block covers 128 queries of one head. grid = (32, 8).
// Per 16-key step: 2x S-mma(m16n8k8, C init = bias) -> ex2 -> pack f16
// (D fragment == A fragment of m16n8k16: register reuse, no smem) -> PV-mma.
// Constant-bias softmax: exact, no row max, no rescale.
// ============================================================================
__global__ __launch_bounds__(256)
void attn_kernel(const float* __restrict__ temperature) {
    __shared__ unsigned sK[CHUNK * 4];      // [key][4 x f16x2 dims]  4 KB
    __shared__ unsigned sVT[8 * CPAD];      // [dim][key/2], padded   4.2 KB

    const int h    = blockIdx.y;
    const int tid  = threadIdx.x;
    const int wid  = tid >> 5;
    const int lane = tid & 31;
    const int r = lane >> 2, m = lane & 3;
    const int q0 = blockIdx.x * 128 + wid * 16;

    const float bias = -fabsf(temperature[h]) * 1.4426950408889634f;

    // Q fragment (persistent): rows q0+r, q0+r+8, dim pair m
    const unsigned* qU = (const unsigned*)g_qh + (size_t)h * HW * 4;
    const unsigned a0q = qU[(q0 + r) * 4 + m];
    const unsigned a1q = qU[(q0 + r + 8) * 4 + m];

    float o0 = 0.f, o1 = 0.f, o2 = 0.f, o3 = 0.f;
    float den0 = 0.f, den1 = 0.f;

    const uint4*    gK4 = (const uint4*)((const unsigned*)g_kh + (size_t)h * HW * 4);
    const unsigned* gV  = (const unsigned*)g_vt + (size_t)h * 8 * (HW / 2);

    const int vd = tid >> 5;            // dim row this thread loads
    const int vj = (tid & 31) * 4;      // uint offset within row

    for (int ch = 0; ch < HW / CHUNK; ch++) {
        __syncthreads();
        ((uint4*)sK)[tid] = gK4[ch * CHUNK + tid];                      // 4 KB
        *(uint4*)(sVT + vd * CPAD + vj) =
            *(const uint4*)(gV + vd * (HW / 2) + ch * (CHUNK / 2) + vj); // 4 KB
        __syncthreads();

#pragma unroll 4
        for (int kb = 0; kb < CHUNK; kb += 16) {
            const unsigned kb0 = sK[(kb + r) * 4 + m];       // keys kb..kb+7
            const unsigned kb1 = sK[(kb + 8 + r) * 4 + m];   // keys kb+8..kb+15

            float s0, s1, s2, s3, t0, t1, t2, t3;
            mma_s(s0, s1, s2, s3, a0q, a1q, kb0, bias);
            mma_s(t0, t1, t2, t3, a0q, a1q, kb1, bias);

            const float e0 = ex2f(s0), e1 = ex2f(s1), e2 = ex2f(s2), e3 = ex2f(s3);
            const float f0 = ex2f(t0), f1 = ex2f(t1), f2 = ex2f(t2), f3 = ex2f(t3);
            den0 += (e0 + e1) + (f0 + f1);
            den1 += (e2 + e3) + (f2 + f3);

            // P fragment = packed exp of S accumulators (layout identity)
            const unsigned p0 = packh2(e0, e1), p1 = packh2(e2, e3);
            const unsigned p2 = packh2(f0, f1), p3 = packh2(f2, f3);

            const unsigned vb0 = sVT[r * CPAD + (kb >> 1) + m];
            const unsigned vb1 = sVT[r * CPAD + (kb >> 1) + m + 4];
            mma_pv(o0, o1, o2, o3, p0, p1, p2, p3, vb0, vb1);
        }
    }

    // row denominators live spread over the quad (lane%4): reduce
    den0 += __shfl_xor_sync(0xffffffffu, den0, 1);
    den0 += __shfl_xor_sync(0xffffffffu, den0, 2);
    den1 += __shfl_xor_sync(0xffffffffu, den1, 1);
    den1 += __shfl_xor_sync(0xffffffffu, den1, 2);
    const float i0 = 1.f / den0, i1 = 1.f / den1;

    // O fragment: rows q0+r (c0,c1) and q0+r+8 (c2,c3); dims 2m, 2m+1
    float* go = g_o + (size_t)h * 8 * HW;
    go[(2 * m    ) * HW + q0 + r    ] = o0 * i0;
    go[(2 * m + 1) * HW + q0 + r    ] = o1 * i0;
    go[(2 * m    ) * HW + q0 + r + 8] = o2 * i1;
    go[(2 * m + 1) * HW + q0 + r + 8] = o3 * i1;
}

// ============================================================================
// Kernel 3: output projection. grid = (32, 8), block = 128.
// ============================================================================
__global__ __launch_bounds__(128)
void outproj_kernel(const float* __restrict__ wout, float* __restrict__ out) {
    __shared__ float4 sW[128];
    const int tid = threadIdx.x;
    const int p   = blockIdx.x * 128 + tid;
    const int og  = blockIdx.y;

    sW[tid] = ((const float4*)wout)[og * 128 + tid];
    __syncthreads();

    float xr[64];
#pragma unroll
    for (int c = 0; c < 64; c++) xr[c] = g_o[c * HW + p];

#pragma unroll
    for (int d = 0; d < 8; d++) {
        float acc = 0.f;
#pragma unroll
        for (int c4 = 0; c4 < 16; c4++) {
            const float4 w = sW[d * 16 + c4];
            acc += w.x * xr[4 * c4 + 0] + w.y * xr[4 * c4 + 1]
                 + w.z * xr[4 * c4 + 2] + w.w * xr[4 * c4 + 3];
        }
        out[(og * 8 + d) * HW + p] = acc;
    }
}

// ============================================================================
extern "C" void kernel_launch(void* const* d_in, const int* in_sizes, int n_in,
                              void* d_out, int out_size) {
    const float* x    = (const float*)d_in[0];
    const float* y    = (const float*)d_in[1];
    const float* wq   = (const float*)d_in[2];
    const float* wkv  = (const float*)d_in[3];
    const float* wout = (const float*)d_in[4];
    const float* temp = (const float*)d_in[5];
    float* out = (float*)d_out;

    prep_kernel<<<dim3(32, 24), 128>>>(x, y, wq, wkv, temp);
    attn_kernel<<<dim3(32, 8), 256>>>(temp);
    outproj_kernel<<<dim3(32, 8), 128>>>(wout, out);
}

// round 10
// speedup vs baseline: 5.5822x; 1.0578x over previous
#include <cuda_runtime.h>
#include <cuda_fp16.h>

#define HW 4096          // tokens
#define NH 8             // heads
#define CHUNK 256        // keys per smem stage
#define CPAD 132         // padded uint stride for V^T rows (CHUNK/2 + 4)

// ---- scratch (device globals; no allocation allowed) ----
__device__ __align__(16) __half g_qh[NH * HW * 8];  // [h][n][8] f16, L2-norm * T*log2e
__device__ __align__(16) __half g_kh[NH * HW * 8];  // [h][m][8] f16, L2-norm
__device__ __align__(16) __half g_vt[NH * 8 * HW];  // [h][d][m] f16 (V transposed)
__device__ float g_o[64 * HW];                      // attention output, [c][p]

// pack two f32 -> f16x2 (lo into low half, hi into high half)
__device__ __forceinline__ unsigned packh2(float lo, float hi) {
    unsigned r; asm("cvt.rn.f16x2.f32 %0,%1,%2;" : "=r"(r) : "f"(hi), "f"(lo)); return r;
}
// packed half2 exp2: ONE MUFU op for two values
__device__ __forceinline__ unsigned ex2h2(unsigned x) {
    unsigned r; asm("ex2.approx.f16x2 %0,%1;" : "=r"(r) : "r"(x)); return r;
}
// S-mma: m16n8k8 f16 inputs, f32 accumulate, scalar C broadcast (bias)
__device__ __forceinline__ void mma_s(float& d0, float& d1, float& d2, float& d3,
                                      unsigned a0, unsigned a1, unsigned b0,
                                      float c) {
    asm("mma.sync.aligned.m16n8k8.row.col.f32.f16.f16.f32 "
        "{%0,%1,%2,%3},{%4,%5},{%6},{%7,%7,%7,%7};"
        : "=f"(d0), "=f"(d1), "=f"(d2), "=f"(d3)
        : "r"(a0), "r"(a1), "r"(b0), "f"(c));
}
// m16n8k16 f16 mma, accumulates in place
__device__ __forceinline__ void mma16(float& d0, float& d1, float& d2, float& d3,
                                      unsigned a0, unsigned a1, unsigned a2, unsigned a3,
                                      unsigned b0, unsigned b1) {
    asm("mma.sync.aligned.m16n8k16.row.col.f32.f16.f16.f32 "
        "{%0,%1,%2,%3},{%4,%5,%6,%7},{%8,%9},{%0,%1,%2,%3};"
        : "+f"(d0), "+f"(d1), "+f"(d2), "+f"(d3)
        : "r"(a0), "r"(a1), "r"(a2), "r"(a3), "r"(b0), "r"(b1));
}

// ============================================================================
// Kernel 1: q/k/v projection + per-head L2 norm; emit f16.
// Loop order fixed: input element loaded ONCE, 8 running accumulators
// (no xr[64] -> no spills/reloads). Weights staged transposed [c][d] in smem.
// grid = (32, 24), block = 128.  task y: 0..7 q, 8..15 k, 16..23 v.
// ============================================================================
__global__ __launch_bounds__(128)
void prep_kernel(const float* __restrict__ x, const float* __restrict__ y,
                 const float* __restrict__ wq, const float* __restrict__ wkv,
                 const float* __restrict__ temperature) {
    __shared__ float sWT[64 * 8];    // [c][d], 2 KB
    const int tid  = threadIdx.x;
    const int p    = blockIdx.x * 128 + tid;
    const int task = blockIdx.y;
    const int typ  = task >> 3;      // 0=q, 1=k, 2=v
    const int h    = task & 7;

    const float* wrow;
    if (typ == 0)      wrow = wq  + (h * 8) * 64;
    else if (typ == 1) wrow = wkv + (h * 8) * 64;
    else               wrow = wkv + (64 + h * 8) * 64;
#pragma unroll
    for (int i = tid; i < 512; i += 128) {      // coalesced global read
        const int d = i >> 6, c = i & 63;
        sWT[c * 8 + d] = wrow[i];
    }
    __syncthreads();

    const float* __restrict__ src = (typ == 0) ? x : y;
    float acc[8];
#pragma unroll
    for (int d = 0; d < 8; d++) acc[d] = 0.f;

#pragma unroll
    for (int c = 0; c < 64; c++) {
        const float xv = src[c * HW + p];                       // 1 LDG, coalesced
        const float4 w0 = *(const float4*)&sWT[c * 8];          // broadcast LDS.128
        const float4 w1 = *(const float4*)&sWT[c * 8 + 4];
        acc[0] += w0.x * xv; acc[1] += w0.y * xv;
        acc[2] += w0.z * xv; acc[3] += w0.w * xv;
        acc[4] += w1.x * xv; acc[5] += w1.y * xv;
        acc[6] += w1.z * xv; acc[7] += w1.w * xv;
    }

    if (typ == 2) {
#pragma unroll
        for (int d = 0; d < 8; d++)
            g_vt[((size_t)h * 8 + d) * HW + p] = __float2half_rn(acc[d]);
        return;
    }

    float ss = 0.f;
#pragma unroll
    for (int d = 0; d < 8; d++) ss += acc[d] * acc[d];
    float scale = 1.f / fmaxf(sqrtf(ss), 1e-12f);
    if (typ == 0) scale *= temperature[h] * 1.4426950408889634f;

    __half2 h01 = __floats2half2_rn(acc[0] * scale, acc[1] * scale);
    __half2 h23 = __floats2half2_rn(acc[2] * scale, acc[3] * scale);
    __half2 h45 = __floats2half2_rn(acc[4] * scale, acc[5] * scale);
    __half2 h67 = __floats2half2_rn(acc[6] * scale, acc[7] * scale);
    uint4 row;
    row.x = *(unsigned*)&h01; row.y = *(unsigned*)&h23;
    row.z = *(unsigned*)&h45; row.w = *(unsigned*)&h67;
    uint4* dst = (typ == 0) ? (uint4*)g_qh : (uint4*)g_kh;
    dst[(size_t)h * HW + p] = row;
}

// ============================================================================
// Kernel 2: flash attention on HMMA. Block = 256 thr (8 warps), warp owns 16
// queries; block covers 128 queries of one head. grid = (32, 8).
// Per 16-key step: 2x S-mma (C init = bias) -> cvt f32x2->f16x2 ->
// ex2.approx.f16x2 (half the MUFU ops) -> PV-mma + DEN-mma (B = ones):
// denominator is the exact row-sum of the same f16 P used in P*V.
// Constant-bias softmax (cosine logits bounded by |T|): exact, no row max.
// ============================================================================
__global__ __launch_bounds__(256)
void attn_kernel(const float* __restrict__ temperature) {
    __shared__ unsigned sK[CHUNK * 4];      // [key][4 x f16x2 dims]  4 KB
    __shared__ unsigned sVT[8 * CPAD];      // [dim][key/2], padded   4.2 KB

    const int h    = blockIdx.y;
    const int tid  = threadIdx.x;
    const int wid  = tid >> 5;
    const int lane = tid & 31;
    const int r = lane >> 2, m = lane & 3;
    const int q0 = blockIdx.x * 128 + wid * 16;

    const float bias = -fabsf(temperature[h]) * 1.4426950408889634f;
    const unsigned ONES = 0x3C003C00u;   // f16x2 (1.0, 1.0)

    // Q fragment (persistent): rows q0+r, q0+r+8, dim pair m
    const unsigned* qU = (const unsigned*)g_qh + (size_t)h * HW * 4;
    const unsigned a0q = qU[(q0 + r) * 4 + m];
    const unsigned a1q = qU[(q0 + r + 8) * 4 + m];

    float o0 = 0.f, o1 = 0.f, o2 = 0.f, o3 = 0.f;        // P*V accum
    float dd0 = 0.f, dd1 = 0.f, dd2 = 0.f, dd3 = 0.f;    // P*ones accum (den)

    const uint4*    gK4 = (const uint4*)((const unsigned*)g_kh + (size_t)h * HW * 4);
    const unsigned* gV  = (const unsigned*)g_vt + (size_t)h * 8 * (HW / 2);

    const int vd = tid >> 5;            // dim row this thread loads
    const int vj = (tid & 31) * 4;      // uint offset within row

    for (int ch = 0; ch < HW / CHUNK; ch++) {
        __syncthreads();
        ((uint4*)sK)[tid] = gK4[ch * CHUNK + tid];                       // 4 KB
        *(uint4*)(sVT + vd * CPAD + vj) =
            *(const uint4*)(gV + vd * (HW / 2) + ch * (CHUNK / 2) + vj); // 4 KB
        __syncthreads();

#pragma unroll 4
        for (int kb = 0; kb < CHUNK; kb += 16) {
            const unsigned kb0 = sK[(kb + r) * 4 + m];       // keys kb..kb+7
            const unsigned kb1 = sK[(kb + 8 + r) * 4 + m];   // keys kb+8..kb+15

            float s0, s1, s2, s3, t0, t1, t2, t3;
            mma_s(s0, s1, s2, s3, a0q, a1q, kb0, bias);
            mma_s(t0, t1, t2, t3, a0q, a1q, kb1, bias);

            // P fragment: packed cvt then packed exp2 (layout identity with
            // the m16n8k16 A fragment)
            const unsigned p0 = ex2h2(packh2(s0, s1));
            const unsigned p1 = ex2h2(packh2(s2, s3));
            const unsigned p2 = ex2h2(packh2(t0, t1));
            const unsigned p3 = ex2h2(packh2(t2, t3));

            const unsigned vb0 = sVT[r * CPAD + (kb >> 1) + m];
            const unsigned vb1 = sVT[r * CPAD + (kb >> 1) + m + 4];
            mma16(o0, o1, o2, o3, p0, p1, p2, p3, vb0, vb1);
            mma16(dd0, dd1, dd2, dd3, p0, p1, p2, p3, ONES, ONES);
        }
    }

    // With B = ones every column of the den accumulator equals the full row
    // sum: dd0 = den(row q0+r), dd2 = den(row q0+r+8). No shuffle needed.
    const float i0 = 1.f / dd0, i1 = 1.f / dd2;

    // O fragment: rows q0+r (o0,o1) and q0+r+8 (o2,o3); dims 2m, 2m+1
    float* go = g_o + (size_t)h * 8 * HW;
    go[(2 * m    ) * HW + q0 + r    ] = o0 * i0;
    go[(2 * m + 1) * HW + q0 + r    ] = o1 * i0;
    go[(2 * m    ) * HW + q0 + r + 8] = o2 * i1;
    go[(2 * m + 1) * HW + q0 + r + 8] = o3 * i1;
}

// ============================================================================
// Kernel 3: output projection, same acc[8] restructure as prep.
// grid = (32, 8), block = 128.
// ============================================================================
__global__ __launch_bounds__(128)
void outproj_kernel(const float* __restrict__ wout, float* __restrict__ out) {
    __shared__ float sWT[64 * 8];    // [c][d] for rows og*8..og*8+7
    const int tid = threadIdx.x;
    const int p   = blockIdx.x * 128 + tid;
    const int og  = blockIdx.y;

#pragma unroll
    for (int i = tid; i < 512; i += 128) {
        const int d = i >> 6, c = i & 63;
        sWT[c * 8 + d] = wout[(og * 8) * 64 + i];
    }
    __syncthreads();

    float acc[8];
#pragma unroll
    for (int d = 0; d < 8; d++) acc[d] = 0.f;

#pragma unroll
    for (int c = 0; c < 64; c++) {
        const float xv = g_o[c * HW + p];
        const float4 w0 = *(const float4*)&sWT[c * 8];
        const float4 w1 = *(const float4*)&sWT[c * 8 + 4];
        acc[0] += w0.x * xv; acc[1] += w0.y * xv;
        acc[2] += w0.z * xv; acc[3] += w0.w * xv;
        acc[4] += w1.x * xv; acc[5] += w1.y * xv;
        acc[6] += w1.z * xv; acc[7] += w1.w * xv;
    }

#pragma unroll
    for (int d = 0; d < 8; d++)
        out[(og * 8 + d) * HW + p] = acc[d];
}

// ============================================================================
extern "C" void kernel_launch(void* const* d_in, const int* in_sizes, int n_in,
                              void* d_out, int out_size) {
    const float* x    = (const float*)d_in[0];
    const float* y    = (const float*)d_in[1];
    const float* wq   = (const float*)d_in[2];
    const float* wkv  = (const float*)d_in[3];
    const float* wout = (const float*)d_in[4];
    const float* temp = (const float*)d_in[5];
    float* out = (float*)d_out;

    prep_kernel<<<dim3(32, 24), 128>>>(x, y, wq, wkv, temp);
    attn_kernel<<<dim3(32, 8), 256>>>(temp);
    outproj_kernel<<<dim3(32, 8), 128>>>(wout, out);
}